// round 5
// baseline (speedup 1.0000x reference)
#include <cuda_runtime.h>

#define NN 2048
#define EE 65536
#define SEQL 5
#define IND 32
#define HID 64
#define OUTD 16

typedef unsigned long long ull;

// ---------------- scratch (device globals; no allocs allowed) ----------------
__device__ float d_deg[NN];
__device__ float d_dinv[NN];
__device__ float d_dself[NN];
__device__ int   d_count[NN];
__device__ int   d_cursor[NN];
__device__ int   d_rowptr[NN + 1];
__device__ int   d_csr_src[EE];
__device__ float d_csr_w[EE];
__device__ __align__(16) float d_P[NN * SEQL * IND];          // aggregated x, [n][t*32+c]
__device__ float d_Wz[IND * HID], d_Wh[IND * HID];            // folded gate weights
__device__ float d_bz[HID], d_bh[HID];
__device__ __align__(16) float d_hs[NN * SEQL * HID];         // [n][t*64+j]
__device__ __align__(16) float d_emb[NN * HID];
__device__ __align__(16) float d_agg[NN * HID];
__device__ __align__(16) float d_r1[NN * HID];
__device__ __align__(16) float d_agg2[NN * HID];
__device__ __align__(16) float d_av[NN * HID];                // emb@Wi1[:64]+bi1
__device__ __align__(16) float d_bv[NN * HID];                // emb@Wi1[64:]

// ---------------- f32x2 packed helpers (Blackwell double-rate fp32) ----------
__device__ __forceinline__ ull f2_add(ull a, ull b) {
    ull r; asm("add.rn.f32x2 %0,%1,%2;" : "=l"(r) : "l"(a), "l"(b)); return r;
}
__device__ __forceinline__ ull f2_fma(ull a, ull b, ull c) {
    ull r; asm("fma.rn.f32x2 %0,%1,%2,%3;" : "=l"(r) : "l"(a), "l"(b), "l"(c)); return r;
}
__device__ __forceinline__ ull f2_relu(ull a) {
    float lo, hi;
    asm("mov.b64 {%0,%1},%2;" : "=f"(lo), "=f"(hi) : "l"(a));
    lo = fmaxf(lo, 0.f); hi = fmaxf(hi, 0.f);
    ull r; asm("mov.b64 %0,{%1,%2};" : "=l"(r) : "f"(lo), "f"(hi)); return r;
}

// ---------------- graph preprocessing ----------------
__global__ void k_init() {
    int i = blockIdx.x * 1024 + threadIdx.x;
    if (i < NN) { d_deg[i] = 1.0f; d_count[i] = 0; d_cursor[i] = 0; }
}

__global__ void k_degcount(const int* __restrict__ ei, const float* __restrict__ ew) {
    int e = blockIdx.x * 1024 + threadIdx.x;
    int dd = ei[EE + e];
    atomicAdd(&d_deg[dd], ew[e]);
    atomicAdd(&d_count[dd], 1);
}

__global__ void k_scan() {   // 1 block, 1024 threads: dinv/dself + inclusive scan -> rowptr
    int t = threadIdx.x;
    __shared__ int s[NN];
    for (int i = t; i < NN; i += 1024) {
        float di = rsqrtf(d_deg[i]);
        d_dinv[i] = di; d_dself[i] = di * di;
        s[i] = d_count[i];
    }
    __syncthreads();
    for (int off = 1; off < NN; off <<= 1) {
        int i1 = t + 1024;
        int v0 = (t >= off)  ? s[t - off]  : 0;
        int v1 = (i1 >= off) ? s[i1 - off] : 0;
        __syncthreads();
        s[t] += v0; s[i1] += v1;
        __syncthreads();
    }
    d_rowptr[t + 1] = s[t];
    d_rowptr[t + 1025] = s[t + 1024];
    if (t == 0) d_rowptr[0] = 0;
}

__global__ void k_scatter(const int* __restrict__ ei, const float* __restrict__ ew) {
    int e = blockIdx.x * 1024 + threadIdx.x;
    int sIdx = ei[e], dd = ei[EE + e];
    int pos = d_rowptr[dd] + atomicAdd(&d_cursor[dd], 1);
    d_csr_src[pos] = sIdx;
    d_csr_w[pos] = d_dinv[sIdx] * ew[e] * d_dinv[dd];
}

// ---------------- fold gate weights: Wz = Wcz@Wlz[:64], bz = bcz@Wlz[:64]+blz --
__global__ void k_weights(const float* __restrict__ Wcz, const float* __restrict__ bcz,
                          const float* __restrict__ Wlz, const float* __restrict__ blz,
                          const float* __restrict__ Wch, const float* __restrict__ bch,
                          const float* __restrict__ Wlh, const float* __restrict__ blh) {
    int gid = blockIdx.x * 1024 + threadIdx.x;     // 2048 threads
    int i = gid >> 6, j = gid & 63;
    float az = 0.f, ah = 0.f;
    for (int k = 0; k < HID; k++) {
        az += Wcz[i * HID + k] * Wlz[k * HID + j];
        ah += Wch[i * HID + k] * Wlh[k * HID + j];
    }
    d_Wz[i * HID + j] = az;
    d_Wh[i * HID + j] = ah;
    if (gid < HID) {
        float bz = blz[gid], bh = blh[gid];
        for (int k = 0; k < HID; k++) {
            bz += bcz[k] * Wlz[k * HID + gid];
            bh += bch[k] * Wlh[k * HID + gid];
        }
        d_bz[gid] = bz; d_bh[gid] = bh;
    }
}

// ---------------- SpMM1: P = Ahat @ x  (160 cols), block per node ------------
__global__ void __launch_bounds__(160) k_spmm1(const float* __restrict__ x) {
    int n = blockIdx.x;
    int tid = threadIdx.x;
    int t = tid >> 5, c = tid & 31;
    __shared__ int   ss[160];
    __shared__ float swt[160];
    int r0 = d_rowptr[n], r1 = d_rowptr[n + 1];
    float acc = d_dself[n] * x[t * NN * IND + n * IND + c];
    for (int base = r0; base < r1; base += 160) {
        int m = min(160, r1 - base);
        if (tid < m) { ss[tid] = d_csr_src[base + tid]; swt[tid] = d_csr_w[base + tid]; }
        __syncthreads();
        for (int k = 0; k < m; k++)
            acc += swt[k] * x[t * NN * IND + ss[k] * IND + c];
        __syncthreads();
    }
    d_P[n * (SEQL * IND) + t * IND + c] = acc;
}

// ---------------- gates: hs = (1 - sigmoid(P Wz + bz)) * tanh(P Wh + bh) -----
__global__ void k_gates() {
    int n = blockIdx.x, t = blockIdx.y, j = threadIdx.x;
    __shared__ float sp[IND];
    if (j < IND) sp[j] = d_P[n * (SEQL * IND) + t * IND + j];
    __syncthreads();
    float az = d_bz[j], ah = d_bh[j];
#pragma unroll
    for (int k = 0; k < IND; k++) {
        float p = sp[k];
        az += p * d_Wz[k * HID + j];
        ah += p * d_Wh[k * HID + j];
    }
    float zg = 1.f / (1.f + expf(-az));
    d_hs[n * (SEQL * HID) + t * HID + j] = (1.f - zg) * tanhf(ah);
}

// ---------------- emb = hs @ Wred + bred  (N x 320 @ 320 x 64) ---------------
__global__ void __launch_bounds__(64) k_emb(const float* __restrict__ Wred,
                                            const float* __restrict__ bred) {
    const int NB = 8;
    int n0 = blockIdx.x * NB, j = threadIdx.x;
    __shared__ __align__(16) float shs[NB][SEQL * HID];
    float* sf = &shs[0][0];
    for (int f = j; f < NB * SEQL * HID; f += 64) sf[f] = d_hs[n0 * (SEQL * HID) + f];
    __syncthreads();
    float acc[NB];
#pragma unroll
    for (int m = 0; m < NB; m++) acc[m] = bred[j];
    for (int k = 0; k < SEQL * HID; k += 4) {
        float w0 = Wred[(k + 0) * HID + j];
        float w1 = Wred[(k + 1) * HID + j];
        float w2 = Wred[(k + 2) * HID + j];
        float w3 = Wred[(k + 3) * HID + j];
#pragma unroll
        for (int m = 0; m < NB; m++) {
            float4 h = *(const float4*)&shs[m][k];
            acc[m] += h.x * w0 + h.y * w1 + h.z * w2 + h.w * w3;
        }
    }
#pragma unroll
    for (int m = 0; m < NB; m++) d_emb[(n0 + m) * HID + j] = acc[m];
}

// ---------------- a' = emb@Wi1[:64]+bi1 ; bv = emb@Wi1[64:] ------------------
__global__ void __launch_bounds__(64) k_ab(const float* __restrict__ Wi1,
                                           const float* __restrict__ bi1) {
    const int NB = 16;
    int n0 = blockIdx.x * NB, j = threadIdx.x;
    __shared__ __align__(16) float se[NB][HID];
    float* sf = &se[0][0];
    for (int f = j; f < NB * HID; f += 64) sf[f] = d_emb[n0 * HID + f];
    __syncthreads();
    float aa[NB], bb[NB];
#pragma unroll
    for (int m = 0; m < NB; m++) { aa[m] = bi1[j]; bb[m] = 0.f; }
    for (int k = 0; k < HID; k += 4) {
        float wa0 = Wi1[(k + 0) * HID + j], wb0 = Wi1[(64 + k + 0) * HID + j];
        float wa1 = Wi1[(k + 1) * HID + j], wb1 = Wi1[(64 + k + 1) * HID + j];
        float wa2 = Wi1[(k + 2) * HID + j], wb2 = Wi1[(64 + k + 2) * HID + j];
        float wa3 = Wi1[(k + 3) * HID + j], wb3 = Wi1[(64 + k + 3) * HID + j];
#pragma unroll
        for (int m = 0; m < NB; m++) {
            float4 e = *(const float4*)&se[m][k];
            aa[m] += e.x * wa0 + e.y * wa1 + e.z * wa2 + e.w * wa3;
            bb[m] += e.x * wb0 + e.y * wb1 + e.z * wb2 + e.w * wb3;
        }
    }
#pragma unroll
    for (int m = 0; m < NB; m++) {
        d_av[(n0 + m) * HID + j] = aa[m];
        d_bv[(n0 + m) * HID + j] = bb[m];
    }
}

// ---------------- SpMM (64 cols): which=0 emb->agg, which=1 r1->agg2 ---------
__global__ void __launch_bounds__(64) k_spmm64(int which) {
    const float* in = which ? d_r1 : d_emb;
    float* out = which ? d_agg2 : d_agg;
    int n = blockIdx.x, c = threadIdx.x;
    __shared__ int   ss[64];
    __shared__ float swt[64];
    int r0 = d_rowptr[n], r1 = d_rowptr[n + 1];
    float acc = d_dself[n] * in[n * HID + c];
    for (int base = r0; base < r1; base += 64) {
        int m = min(64, r1 - base);
        if (c < m) { ss[c] = d_csr_src[base + c]; swt[c] = d_csr_w[base + c]; }
        __syncthreads();
        for (int k = 0; k < m; k++)
            acc += swt[k] * in[ss[k] * HID + c];
        __syncthreads();
    }
    out[n * HID + c] = acc;
}

// ---------------- gcn1 tail: h1 = agg@Wc1+bc1 -> LN -> relu -> r1 ------------
__global__ void __launch_bounds__(64) k_ln1(const float* __restrict__ Wc1, const float* __restrict__ bc1,
                                            const float* __restrict__ g1, const float* __restrict__ be1) {
    int n = blockIdx.x, j = threadIdx.x;
    __shared__ float sa[HID];
    __shared__ float rbuf[4];
    sa[j] = d_agg[n * HID + j];
    __syncthreads();
    float h = bc1[j];
#pragma unroll
    for (int k = 0; k < HID; k++) h += sa[k] * Wc1[k * HID + j];
    float v = h;
#pragma unroll
    for (int o = 16; o > 0; o >>= 1) v += __shfl_xor_sync(0xffffffffu, v, o);
    if ((j & 31) == 0) rbuf[j >> 5] = v;
    __syncthreads();
    float mu = (rbuf[0] + rbuf[1]) * (1.f / 64.f);
    float d = h - mu;
    float v2 = d * d;
#pragma unroll
    for (int o = 16; o > 0; o >>= 1) v2 += __shfl_xor_sync(0xffffffffu, v2, o);
    if ((j & 31) == 0) rbuf[(j >> 5) + 2] = v2;
    __syncthreads();
    float var = (rbuf[2] + rbuf[3]) * (1.f / 64.f);
    d_r1[n * HID + j] = fmaxf(0.f, d * rsqrtf(var + 1e-5f) * g1[j] + be1[j]);
}

// ---------------- gcn2 tail + node_pred --------------------------------------
__global__ void __launch_bounds__(64) k_ln2(const float* __restrict__ Wc2, const float* __restrict__ bc2,
                                            const float* __restrict__ g2, const float* __restrict__ be2,
                                            const float* __restrict__ Wout, const float* __restrict__ bout,
                                            float* __restrict__ outp) {
    int n = blockIdx.x, j = threadIdx.x;
    __shared__ float sa[HID];
    __shared__ float sr[HID];
    __shared__ float rbuf[4];
    sa[j] = d_agg2[n * HID + j];
    __syncthreads();
    float h = bc2[j];
#pragma unroll
    for (int k = 0; k < HID; k++) h += sa[k] * Wc2[k * HID + j];
    float v = h;
#pragma unroll
    for (int o = 16; o > 0; o >>= 1) v += __shfl_xor_sync(0xffffffffu, v, o);
    if ((j & 31) == 0) rbuf[j >> 5] = v;
    __syncthreads();
    float mu = (rbuf[0] + rbuf[1]) * (1.f / 64.f);
    float d = h - mu;
    float v2 = d * d;
#pragma unroll
    for (int o = 16; o > 0; o >>= 1) v2 += __shfl_xor_sync(0xffffffffu, v2, o);
    if ((j & 31) == 0) rbuf[(j >> 5) + 2] = v2;
    __syncthreads();
    float var = (rbuf[2] + rbuf[3]) * (1.f / 64.f);
    float r = fmaxf(0.f, d * rsqrtf(var + 1e-5f) * g2[j] + be2[j]);
    sr[j] = r;
    __syncthreads();
    if (j < OUTD) {
        float o = bout[j];
#pragma unroll
        for (int k = 0; k < HID; k++) o += sr[k] * Wout[k * OUTD + j];
        outp[n * OUTD + j] = o;
    }
}

// ---------------- scores: relu(a_i + b_j) . w  (f32x2 packed) ----------------
__global__ void __launch_bounds__(256) k_scores(const float* __restrict__ Wi2,
                                                const float* __restrict__ bi2,
                                                float* __restrict__ outp) {
    __shared__ __align__(16) float sA[64][66];
    __shared__ __align__(16) float sB[64][66];
    __shared__ __align__(16) float sW[64];
    int tx = threadIdx.x, ty = threadIdx.y;
    int tid = ty * 16 + tx;
    int i0 = blockIdx.y * 64, j0 = blockIdx.x * 64;
    for (int f = tid; f < 64 * 32; f += 256) {
        int r = f >> 5, c2 = f & 31;
        float2 va = *(const float2*)&d_av[(i0 + r) * HID + 2 * c2];
        float2 vb = *(const float2*)&d_bv[(j0 + r) * HID + 2 * c2];
        *(float2*)&sA[r][2 * c2] = va;
        *(float2*)&sB[r][2 * c2] = vb;
    }
    if (tid < 64) sW[tid] = Wi2[tid];
    __syncthreads();

    ull acc[4][4];
#pragma unroll
    for (int r = 0; r < 4; r++)
#pragma unroll
        for (int c = 0; c < 4; c++) acc[r][c] = 0ull;

#pragma unroll 4
    for (int h = 0; h < 32; h++) {
        ull w2 = *(const ull*)&sW[2 * h];
        ull A[4], B[4];
#pragma unroll
        for (int r = 0; r < 4; r++) A[r] = *(const ull*)&sA[ty * 4 + r][2 * h];
#pragma unroll
        for (int c = 0; c < 4; c++) B[c] = *(const ull*)&sB[tx * 4 + c][2 * h];
#pragma unroll
        for (int r = 0; r < 4; r++)
#pragma unroll
            for (int c = 0; c < 4; c++) {
                ull t = f2_add(A[r], B[c]);
                t = f2_relu(t);
                acc[r][c] = f2_fma(t, w2, acc[r][c]);
            }
    }

    float bb = bi2[0];
    float* sc = outp + NN * OUTD;
#pragma unroll
    for (int r = 0; r < 4; r++) {
        float4 o;
        float res[4];
#pragma unroll
        for (int c = 0; c < 4; c++) {
            float lo, hi;
            asm("mov.b64 {%0,%1},%2;" : "=f"(lo), "=f"(hi) : "l"(acc[r][c]));
            res[c] = lo + hi + bb;
        }
        o.x = res[0]; o.y = res[1]; o.z = res[2]; o.w = res[3];
        *(float4*)&sc[(i0 + ty * 4 + r) * NN + j0 + tx * 4] = o;
    }
}

// ---------------- launcher ----------------------------------------------------
extern "C" void kernel_launch(void* const* d_in, const int* in_sizes, int n_in,
                              void* d_out, int out_size) {
    (void)out_size;
    const float* x = nullptr;
    const int* ei = nullptr;
    const float* ew = nullptr;
    const float* W[28];
    int wi = 0;
    for (int i = 0; i < n_in; i++) {
        int s = in_sizes[i];
        if (s == SEQL * NN * IND)      x  = (const float*)d_in[i];
        else if (s == 2 * EE)          ei = (const int*)d_in[i];
        else if (s == EE)              ew = (const float*)d_in[i];
        else if (wi < 28)              W[wi++] = (const float*)d_in[i];
    }
    // order (both dict/signature agree): Wcz bcz Wlz blz Wcr bcr Wlr blr
    //  Wch bch Wlh blh Wred bred Wc1 bc1 Wc2 bc2 g1 be1 g2 be2 Wout bout Wi1 bi1 Wi2 bi2
    const float *Wcz = W[0],  *bcz = W[1],  *Wlz = W[2],  *blz = W[3];
    const float *Wch = W[8],  *bch = W[9],  *Wlh = W[10], *blh = W[11];
    const float *Wred = W[12], *bred = W[13];
    const float *Wc1 = W[14], *bc1 = W[15], *Wc2 = W[16], *bc2 = W[17];
    const float *g1 = W[18],  *be1 = W[19], *g2 = W[20],  *be2 = W[21];
    const float *Wout = W[22], *bout = W[23];
    const float *Wi1 = W[24], *bi1 = W[25], *Wi2 = W[26], *bi2 = W[27];
    float* outp = (float*)d_out;

    k_init<<<2, 1024>>>();
    k_degcount<<<EE / 1024, 1024>>>(ei, ew);
    k_scan<<<1, 1024>>>();
    k_scatter<<<EE / 1024, 1024>>>(ei, ew);
    k_weights<<<2, 1024>>>(Wcz, bcz, Wlz, blz, Wch, bch, Wlh, blh);
    k_spmm1<<<NN, 160>>>(x);
    k_gates<<<dim3(NN, SEQL), 64>>>();
    k_emb<<<NN / 8, 64>>>(Wred, bred);
    k_ab<<<NN / 16, 64>>>(Wi1, bi1);
    k_spmm64<<<NN, 64>>>(0);
    k_ln1<<<NN, 64>>>(Wc1, bc1, g1, be1);
    k_spmm64<<<NN, 64>>>(1);
    k_ln2<<<NN, 64>>>(Wc2, bc2, g2, be2, Wout, bout, outp);
    k_scores<<<dim3(NN / 64, NN / 64), dim3(16, 16)>>>(Wi2, bi2, outp);
}